// round 1
// baseline (speedup 1.0000x reference)
#include <cuda_runtime.h>
#include <math.h>

// RoI-Align FPN extractor.
// Shapes (fixed by problem): feats lvl i: (2, 256, 200>>i, 336>>i) fp32, strides 4<<i.
// rois: (512, 5) [batch, x1, y1, x2, y2]. out: (512, 256, 7, 7) fp32.

static constexpr int NS   = 14;    // OUT*SR sample grid per axis
static constexpr int NCH  = 256;
static constexpr int BUFN = 1408;  // per-warp smem staging floats (worst region ~1100)
static constexpr int NW   = 8;     // warps per block

__device__ __forceinline__ float bin_val(const float* base,
                                         const int* oy, const float* wy,
                                         const int* ox, const float* wx)
{
    float acc = 0.0f;
#pragma unroll
    for (int i = 0; i < 4; i++) {
        const float* rp = base + oy[i];
        float ra = 0.0f;
#pragma unroll
        for (int j = 0; j < 4; j++)
            ra = fmaf(wx[j], rp[ox[j]], ra);
        acc = fmaf(wy[i], ra, acc);
    }
    return acc;
}

__global__ void __launch_bounds__(256)
roi_align_fpn_kernel(const float* __restrict__ f0, const float* __restrict__ f1,
                     const float* __restrict__ f2, const float* __restrict__ f3,
                     const float* __restrict__ rois, float* __restrict__ out)
{
    __shared__ float s_wy0[NS], s_wy1[NS], s_wx0[NS], s_wx1[NS];
    __shared__ int   s_iy0[NS], s_iy1[NS], s_ix0[NS], s_ix1[NS];
    __shared__ int   s_lvl, s_b;
    __shared__ float s_buf[NW][BUFN];

    const int n   = blockIdx.x;
    const int tid = threadIdx.x;

    if (tid == 0) {
        const float* r = rois + (size_t)n * 5;
        float rb = r[0], rx1 = r[1], ry1 = r[2], rx2 = r[3], ry2 = r[4];
        float sc = sqrtf((rx2 - rx1) * (ry2 - ry1));
        int lvl = (int)floor(log2((double)sc / 56.0 + 1e-6));
        lvl = lvl < 0 ? 0 : (lvl > 3 ? 3 : lvl);
        s_lvl = lvl;
        s_b   = (int)rb;
        const int H = 200 >> lvl, W = 336 >> lvl;
        const float isc = 1.0f / (float)(4 << lvl);
        float x1 = rx1 * isc - 0.5f, y1 = ry1 * isc - 0.5f;
        float x2 = rx2 * isc - 0.5f, y2 = ry2 * isc - 0.5f;
        float bw = (x2 - x1) / 7.0f, bh = (y2 - y1) / 7.0f;
#pragma unroll 1
        for (int i = 0; i < NS; i++) {
            float off = (float)(i >> 1) + ((float)(i & 1) + 0.5f) * 0.5f;
            // x axis
            {
                float c  = x1 + off * bw;
                float v  = (c >= -1.0f && c <= (float)W) ? 1.0f : 0.0f;
                float cc = fminf(fmaxf(c, 0.0f), (float)W - 1.0f);
                int lo   = (int)floorf(cc);
                int hi   = min(lo + 1, W - 1);
                float fr = cc - (float)lo;
                s_ix0[i] = lo; s_ix1[i] = hi;
                s_wx0[i] = v * (1.0f - fr); s_wx1[i] = v * fr;
            }
            // y axis
            {
                float c  = y1 + off * bh;
                float v  = (c >= -1.0f && c <= (float)H) ? 1.0f : 0.0f;
                float cc = fminf(fmaxf(c, 0.0f), (float)H - 1.0f);
                int lo   = (int)floorf(cc);
                int hi   = min(lo + 1, H - 1);
                float fr = cc - (float)lo;
                s_iy0[i] = lo; s_iy1[i] = hi;
                s_wy0[i] = v * (1.0f - fr); s_wy1[i] = v * fr;
            }
        }
    }
    __syncthreads();

    const int lvl = s_lvl, b = s_b;
    const int H = 200 >> lvl, W = 336 >> lvl;
    const int HW = H * W;
    const float* fb = (lvl == 0) ? f0 : (lvl == 1) ? f1 : (lvl == 2) ? f2 : f3;
    fb += (size_t)b * NCH * HW;

    // sample coords are monotonically increasing -> region bounds from endpoints
    const int ymin  = s_iy0[0];
    const int xmin  = s_ix0[0];
    const int rowsN = s_iy1[NS - 1] - ymin + 1;
    const int colsN = s_ix1[NS - 1] - xmin + 1;
    const int colsPad = colsN | 1;                 // odd stride -> spread smem banks
    const bool useSmem = (rowsN * colsPad) <= BUFN;

    const int warp = tid >> 5, lane = tid & 31;
    const int stride = useSmem ? colsPad : W;
    const int oy0    = useSmem ? ymin : 0;
    const int ox0    = useSmem ? xmin : 0;

    // Per-lane bin precompute: bins {lane, lane+32}. 4 row-offsets/weights and
    // 4 col-offsets/weights per bin; the 4x4 outer product enumerates exactly
    // the 4 samples x 4 bilinear taps of the bin.
    int   offY[2][4], offX[2][4];
    float wY[2][4], wX[2][4];
    bool  act[2];
#pragma unroll
    for (int p = 0; p < 2; p++) {
        int bin = lane + 32 * p;
        act[p] = bin < 49;
        int bb = act[p] ? bin : 0;
        int by = bb / 7, bx = bb - by * 7;
        int r0 = 2 * by, c0 = 2 * bx;
        offY[p][0] = (s_iy0[r0]     - oy0) * stride; wY[p][0] = s_wy0[r0];
        offY[p][1] = (s_iy1[r0]     - oy0) * stride; wY[p][1] = s_wy1[r0];
        offY[p][2] = (s_iy0[r0 + 1] - oy0) * stride; wY[p][2] = s_wy0[r0 + 1];
        offY[p][3] = (s_iy1[r0 + 1] - oy0) * stride; wY[p][3] = s_wy1[r0 + 1];
        offX[p][0] = s_ix0[c0]     - ox0;            wX[p][0] = s_wx0[c0];
        offX[p][1] = s_ix1[c0]     - ox0;            wX[p][1] = s_wx1[c0];
        offX[p][2] = s_ix0[c0 + 1] - ox0;            wX[p][2] = s_wx0[c0 + 1];
        offX[p][3] = s_ix1[c0 + 1] - ox0;            wX[p][3] = s_wx1[c0 + 1];
    }

    // magic divide by colsN (exact for i < 2^16)
    const unsigned umagic = 0xFFFFFFFFu / (unsigned)colsN + 1u;
    const int stageTot = rowsN * colsN;
    float* bufw  = s_buf[warp];
    float* oBase = out + (size_t)n * NCH * 49;

    for (int k = 0; k < NCH / NW; k++) {
        const int c = warp * (NCH / NW) + k;
        const float* src = fb + (size_t)c * HW;

        if (useSmem) {
            // coalesced staging of the bounding region into this warp's buffer
            for (int i = lane; i < stageTot; i += 32) {
                unsigned r = (unsigned)(((unsigned long long)i * umagic) >> 32);
                int x = i - (int)r * colsN;
                bufw[(int)r * colsPad + x] = __ldg(src + (ymin + (int)r) * W + xmin + x);
            }
            __syncwarp();
#pragma unroll
            for (int p = 0; p < 2; p++) {
                if (!act[p]) continue;
                float v = bin_val(bufw, offY[p], wY[p], offX[p], wX[p]);
                oBase[(size_t)c * 49 + lane + 32 * p] = 0.25f * v;
            }
            __syncwarp();   // all lanes done reading before next stage overwrites
        } else {
            // fallback: region larger than buffer (shouldn't trigger for this
            // input distribution) -> gather directly from gmem
#pragma unroll
            for (int p = 0; p < 2; p++) {
                if (!act[p]) continue;
                float v = bin_val(src, offY[p], wY[p], offX[p], wX[p]);
                oBase[(size_t)c * 49 + lane + 32 * p] = 0.25f * v;
            }
        }
    }
}

extern "C" void kernel_launch(void* const* d_in, const int* in_sizes, int n_in,
                              void* d_out, int out_size)
{
    const float* f0   = (const float*)d_in[0];
    const float* f1   = (const float*)d_in[1];
    const float* f2   = (const float*)d_in[2];
    const float* f3   = (const float*)d_in[3];
    const float* rois = (const float*)d_in[4];
    float* out = (float*)d_out;

    const int nroi = in_sizes[4] / 5;   // 512
    roi_align_fpn_kernel<<<nroi, 256>>>(f0, f1, f2, f3, rois, out);
}

// round 5
// speedup vs baseline: 1.1196x; 1.1196x over previous
#include <cuda_runtime.h>
#include <cstdint>
#include <math.h>

// RoI-Align FPN extractor, R2 logic (R4 resubmit; R3 fixed <cstdint>).
// feats lvl i: (2, 256, 200>>i, 336>>i) fp32, stride 4<<i.
// rois: (512,5). out: (512, 256, 7, 7) fp32.
//
// Grid: nroi * 4 blocks (4 channel slices of 64 ch). Block: 256 thr, 8 warps,
// each warp owns 8 channels sequentially: cp.async-stage the roi's bounding
// region into a warp-private smem buffer, then 49 bins are computed by lanes
// from smem using per-bin coefficient tables (also in smem).

static constexpr int NS    = 14;    // OUT*SR samples per axis
static constexpr int NCH   = 256;
static constexpr int BUFN  = 1216;  // per-warp staging floats (worst ~1179)
static constexpr int NW    = 8;     // warps per block
static constexpr int CPW   = 8;     // channels per warp
static constexpr int BINPAD= 52;    // padded bin dim for coef tables

__device__ __forceinline__ void cp_async4(uint32_t dst_smem, const float* src)
{
    asm volatile("cp.async.ca.shared.global [%0], [%1], 4;\n"
                 :: "r"(dst_smem), "l"(src));
}
__device__ __forceinline__ void cp_async_wait_all()
{
    asm volatile("cp.async.commit_group;\n");
    asm volatile("cp.async.wait_group 0;\n" ::: "memory");
}

__global__ void __launch_bounds__(256, 5)
roi_align_fpn_kernel(const float* __restrict__ f0, const float* __restrict__ f1,
                     const float* __restrict__ f2, const float* __restrict__ f3,
                     const float* __restrict__ rois, float* __restrict__ out)
{
    __shared__ float s_wy0[NS], s_wy1[NS], s_wx0[NS], s_wx1[NS];
    __shared__ int   s_iy0[NS], s_iy1[NS], s_ix0[NS], s_ix1[NS];
    __shared__ int   s_lvl, s_b;
    // coefficient tables: [tap i][bin] = {offset-as-float-bits, weight}
    __shared__ float2 s_cy[4][BINPAD];
    __shared__ float2 s_cx[4][BINPAD];
    __shared__ float  s_buf[NW][BUFN];

    const int n     = blockIdx.x >> 2;        // roi index
    const int slice = blockIdx.x & 3;         // 64-channel slice
    const int tid   = threadIdx.x;

    if (tid == 0) {
        const float* r = rois + (size_t)n * 5;
        float rb = r[0], rx1 = r[1], ry1 = r[2], rx2 = r[3], ry2 = r[4];
        float sc = sqrtf((rx2 - rx1) * (ry2 - ry1));
        int lvl = (int)floor(log2((double)sc / 56.0 + 1e-6));
        lvl = lvl < 0 ? 0 : (lvl > 3 ? 3 : lvl);
        s_lvl = lvl;
        s_b   = (int)rb;
        const int H = 200 >> lvl, W = 336 >> lvl;
        const float isc = 1.0f / (float)(4 << lvl);
        float x1 = rx1 * isc - 0.5f, y1 = ry1 * isc - 0.5f;
        float x2 = rx2 * isc - 0.5f, y2 = ry2 * isc - 0.5f;
        float bw = (x2 - x1) / 7.0f, bh = (y2 - y1) / 7.0f;
#pragma unroll 1
        for (int i = 0; i < NS; i++) {
            float off = (float)(i >> 1) + ((float)(i & 1) + 0.5f) * 0.5f;
            {
                float c  = x1 + off * bw;
                float v  = (c >= -1.0f && c <= (float)W) ? 1.0f : 0.0f;
                float cc = fminf(fmaxf(c, 0.0f), (float)W - 1.0f);
                int lo   = (int)floorf(cc);
                int hi   = min(lo + 1, W - 1);
                float fr = cc - (float)lo;
                s_ix0[i] = lo; s_ix1[i] = hi;
                s_wx0[i] = v * (1.0f - fr); s_wx1[i] = v * fr;
            }
            {
                float c  = y1 + off * bh;
                float v  = (c >= -1.0f && c <= (float)H) ? 1.0f : 0.0f;
                float cc = fminf(fmaxf(c, 0.0f), (float)H - 1.0f);
                int lo   = (int)floorf(cc);
                int hi   = min(lo + 1, H - 1);
                float fr = cc - (float)lo;
                s_iy0[i] = lo; s_iy1[i] = hi;
                s_wy0[i] = v * (1.0f - fr); s_wy1[i] = v * fr;
            }
        }
    }
    __syncthreads();

    const int lvl = s_lvl, b = s_b;
    const int H = 200 >> lvl, W = 336 >> lvl;
    const int HW = H * W;
    const float* fb = (lvl == 0) ? f0 : (lvl == 1) ? f1 : (lvl == 2) ? f2 : f3;
    fb += (size_t)b * NCH * HW;

    // sample coords increase monotonically -> region bounds from endpoints
    const int ymin  = s_iy0[0];
    const int xmin  = s_ix0[0];
    const int rowsN = s_iy1[NS - 1] - ymin + 1;
    const int colsN = s_ix1[NS - 1] - xmin + 1;
    const int colsPad = colsN | 1;                 // odd stride -> spread banks
    const bool useSmem = (rowsN * colsPad) <= BUFN;

    const int stride = useSmem ? colsPad : W;
    const int oy0    = useSmem ? ymin : 0;
    const int ox0    = useSmem ? xmin : 0;

    // Build per-bin coefficient tables (49 bins x 4 taps, y and x axes).
    if (tid < 196) {
        const int i   = tid / 49;      // tap index
        const int bin = tid - i * 49;
        const int by  = bin / 7, bx = bin - by * 7;
        const int r   = 2 * by + (i >> 1);
        const int c   = 2 * bx + (i >> 1);
        int   iy = (i & 1) ? s_iy1[r] : s_iy0[r];
        float wy = (i & 1) ? s_wy1[r] : s_wy0[r];
        int   ix = (i & 1) ? s_ix1[c] : s_ix0[c];
        float wx = (i & 1) ? s_wx1[c] : s_wx0[c];
        s_cy[i][bin] = make_float2(__int_as_float((iy - oy0) * stride), wy);
        s_cx[i][bin] = make_float2(__int_as_float(ix - ox0), wx);
    }
    __syncthreads();

    const int warp = tid >> 5, lane = tid & 31;
    const unsigned umagic = 0xFFFFFFFFu / (unsigned)colsN + 1u;   // exact for i < 2^16
    const int stageTot = rowsN * colsN;
    float* bufw = s_buf[warp];
    const uint32_t bufw_sm = (uint32_t)__cvta_generic_to_shared(bufw);
    float* oBase = out + ((size_t)n * NCH + slice * 64 + warp * CPW) * 49;

    // Hoist x-axis coefficients for this lane's two bins (loop-invariant).
    const int bin0 = lane, bin1 = lane + 32;
    const bool act1 = bin1 < 49;
    const int bb1 = act1 ? bin1 : 0;
    float2 cx0[4], cx1[4];
#pragma unroll
    for (int j = 0; j < 4; j++) { cx0[j] = s_cx[j][bin0]; cx1[j] = s_cx[j][bb1]; }

    for (int k = 0; k < CPW; k++) {
        const int c = slice * 64 + warp * CPW + k;
        const float* src = fb + (size_t)c * HW;

        if (useSmem) {
            // coalesced cp.async staging of the bounding region
            for (int i = lane; i < stageTot; i += 32) {
                unsigned r = (unsigned)(((unsigned long long)i * umagic) >> 32);
                int x = i - (int)r * colsN;
                cp_async4(bufw_sm + 4u * ((int)r * colsPad + x),
                          src + (ymin + (int)r) * W + xmin + x);
            }
            cp_async_wait_all();
            __syncwarp();
            {
                float acc = 0.0f;
#pragma unroll
                for (int i = 0; i < 4; i++) {
                    float2 cy = s_cy[i][bin0];
                    const float* rp = bufw + __float_as_int(cy.x);
                    float ra = 0.0f;
#pragma unroll
                    for (int j = 0; j < 4; j++)
                        ra = fmaf(cx0[j].y, rp[__float_as_int(cx0[j].x)], ra);
                    acc = fmaf(cy.y, ra, acc);
                }
                oBase[(size_t)k * 49 + bin0] = 0.25f * acc;
            }
            if (act1) {
                float acc = 0.0f;
#pragma unroll
                for (int i = 0; i < 4; i++) {
                    float2 cy = s_cy[i][bin1];
                    const float* rp = bufw + __float_as_int(cy.x);
                    float ra = 0.0f;
#pragma unroll
                    for (int j = 0; j < 4; j++)
                        ra = fmaf(cx1[j].y, rp[__float_as_int(cx1[j].x)], ra);
                    acc = fmaf(cy.y, ra, acc);
                }
                oBase[(size_t)k * 49 + bin1] = 0.25f * acc;
            }
            __syncwarp();   // all lanes done reading before next stage overwrites
        } else {
            // rare fallback: region larger than buffer -> gather from gmem
#pragma unroll 1
            for (int p = 0; p < 2; p++) {
                const int bin = lane + 32 * p;
                if (bin >= 49) break;
                const float2* cx = p ? cx1 : cx0;
                float acc = 0.0f;
#pragma unroll
                for (int i = 0; i < 4; i++) {
                    float2 cy = s_cy[i][bin];
                    const float* rp = src + __float_as_int(cy.x);
                    float ra = 0.0f;
#pragma unroll
                    for (int j = 0; j < 4; j++)
                        ra = fmaf(cx[j].y, __ldg(rp + __float_as_int(cx[j].x)), ra);
                    acc = fmaf(cy.y, ra, acc);
                }
                oBase[(size_t)k * 49 + bin] = 0.25f * acc;
            }
        }
    }
}

extern "C" void kernel_launch(void* const* d_in, const int* in_sizes, int n_in,
                              void* d_out, int out_size)
{
    const float* f0   = (const float*)d_in[0];
    const float* f1   = (const float*)d_in[1];
    const float* f2   = (const float*)d_in[2];
    const float* f3   = (const float*)d_in[3];
    const float* rois = (const float*)d_in[4];
    float* out = (float*)d_out;

    const int nroi = in_sizes[4] / 5;   // 512
    roi_align_fpn_kernel<<<nroi * 4, 256>>>(f0, f1, f2, f3, rois, out);
}